// round 10
// baseline (speedup 1.0000x reference)
#include <cuda_runtime.h>
#include <math.h>

#define H      1024
#define BATCH  32
#define TSTEPS 512
#define INDIM  512
#define G4     (4*H)
#define NCTA9  128
#define NTHR9  512   // 16 warps = 8 pairs; pair = 1 unit, split over j halves

// ---------------- scratch ----------------
__device__ float g_xz[(size_t)BATCH * TSTEPS * G4];   // 268 MB: x@W, [B*T, 4H]
__device__ float g_UT[(size_t)G4 * H];                // 16 MB: U transposed [4H][H]
__device__ float g_h[2][BATCH * H];                   // ping-pong h, [b][j]
__device__ unsigned g_bar_cnt[8 * 32];                // 8 monotonic epoch counters, 128B stride

// ---------------- helpers ----------------
__device__ __forceinline__ void fma2(unsigned long long& d, unsigned long long a,
                                     unsigned long long b) {
    asm("fma.rn.f32x2 %0, %1, %2, %0;" : "+l"(d) : "l"(a), "l"(b));
}
__device__ __forceinline__ float hsum2(unsigned long long v) {
    float x, y;
    asm("mov.b64 {%0, %1}, %2;" : "=f"(x), "=f"(y) : "l"(v));
    return x + y;
}
__device__ __forceinline__ unsigned long long packdup(float a) {
    unsigned long long d;
    asm("mov.b64 %0, {%1, %1};" : "=l"(d) : "f"(a));
    return d;
}
__device__ __forceinline__ unsigned ld_cg_u32(const unsigned* p) {
    unsigned v;
    asm volatile("ld.global.cg.u32 %0, [%1];" : "=r"(v) : "l"(p) : "memory");
    return v;
}
__device__ __forceinline__ void cp_async16(unsigned smem_addr, const void* gptr) {
    asm volatile("cp.async.cg.shared.global [%0], [%1], 16;"
                 :: "r"(smem_addr), "l"(gptr) : "memory");
}
__device__ __forceinline__ void cp_commit() {
    asm volatile("cp.async.commit_group;" ::: "memory");
}
template <int N>
__device__ __forceinline__ void cp_wait() {
    asm volatile("cp.async.wait_group %0;" :: "n"(N) : "memory");
}

// ---------------- prep: zero h0 + barrier state (every replay) ----------------
__global__ void zero_h_kernel() {
    int i = blockIdx.x * blockDim.x + threadIdx.x;
    if (i < 2 * BATCH * H) ((float*)g_h)[i] = 0.f;
    if (i < 8 * 32) g_bar_cnt[i] = 0u;
}

// ---------------- transpose U [H][4H] -> UT [4H][H] ----------------
__global__ void transpose_u_kernel(const float* __restrict__ U) {
    __shared__ float tile[32][33];
    int x = blockIdx.x * 32 + threadIdx.x;
    int y = blockIdx.y * 32 + threadIdx.y;
    tile[threadIdx.y][threadIdx.x] = U[(size_t)y * G4 + x];
    __syncthreads();
    int ox = blockIdx.y * 32 + threadIdx.x;
    int oy = blockIdx.x * 32 + threadIdx.y;
    g_UT[(size_t)oy * H + ox] = tile[threadIdx.x][threadIdx.y];
}

// ---------------- input GEMM: g_xz = x @ W (f32x2 packed) ----------------
__global__ __launch_bounds__(256) void sgemm_xw_kernel(const float* __restrict__ A,
                                                       const float* __restrict__ Bm) {
    const int K = INDIM, N = G4;
    __shared__ float As[8][128];
    __shared__ float Bs[8][128];
    const int tid = threadIdx.x;
    const int bm = blockIdx.y, bn = blockIdx.x;
    const int arow = tid >> 1, acol = (tid & 1) << 2;
    const int brow = tid >> 5, bcol = (tid & 31) << 2;
    const int tx = tid & 15, ty = tid >> 4;

    unsigned long long acc2[4][8];
#pragma unroll
    for (int i = 0; i < 4; i++)
#pragma unroll
        for (int j = 0; j < 8; j++) acc2[i][j] = 0ull;

    const float* Ap = A + (size_t)(bm * 128 + arow) * K + acol;
    const float* Bp = Bm + (size_t)brow * N + bn * 128 + bcol;

    for (int k0 = 0; k0 < K; k0 += 8) {
        float4 av = *(const float4*)(Ap + k0);
        As[acol + 0][arow] = av.x;
        As[acol + 1][arow] = av.y;
        As[acol + 2][arow] = av.z;
        As[acol + 3][arow] = av.w;
        float4 bv = *(const float4*)(Bp + (size_t)k0 * N);
        *(float4*)&Bs[brow][bcol] = bv;
        __syncthreads();
#pragma unroll
        for (int kk = 0; kk < 8; kk++) {
            ulonglong2 a01 = *(const ulonglong2*)&As[kk][ty * 8];
            ulonglong2 a23 = *(const ulonglong2*)&As[kk][ty * 8 + 4];
            unsigned long long a2[4] = {a01.x, a01.y, a23.x, a23.y};
            float4 b0 = *(const float4*)&Bs[kk][tx * 8];
            float4 b1 = *(const float4*)&Bs[kk][tx * 8 + 4];
            unsigned long long b2[8];
            b2[0] = packdup(b0.x); b2[1] = packdup(b0.y);
            b2[2] = packdup(b0.z); b2[3] = packdup(b0.w);
            b2[4] = packdup(b1.x); b2[5] = packdup(b1.y);
            b2[6] = packdup(b1.z); b2[7] = packdup(b1.w);
#pragma unroll
            for (int i = 0; i < 4; i++)
#pragma unroll
                for (int j = 0; j < 8; j++) fma2(acc2[i][j], a2[i], b2[j]);
        }
        __syncthreads();
    }
    float* Cp = g_xz + (size_t)(bm * 128 + ty * 8) * N + bn * 128 + tx * 8;
#pragma unroll
    for (int i = 0; i < 4; i++) {
        float r0[8], r1[8];
#pragma unroll
        for (int j = 0; j < 8; j++) {
            float x, y;
            asm("mov.b64 {%0, %1}, %2;" : "=f"(x), "=f"(y) : "l"(acc2[i][j]));
            r0[j] = x; r1[j] = y;
        }
        *(float4*)(Cp + (size_t)(2 * i) * N)     = make_float4(r0[0], r0[1], r0[2], r0[3]);
        *(float4*)(Cp + (size_t)(2 * i) * N + 4) = make_float4(r0[4], r0[5], r0[6], r0[7]);
        *(float4*)(Cp + (size_t)(2 * i + 1) * N)     = make_float4(r1[0], r1[1], r1[2], r1[3]);
        *(float4*)(Cp + (size_t)(2 * i + 1) * N + 4) = make_float4(r1[4], r1[5], r1[6], r1[7]);
    }
}

// ---------------- persistent recurrent kernel v9 ----------------
// 128 CTAs x 512 thr (16 warps = 4/SMSP for latency hiding).
// Warp pair (2k, 2k+1) -> unit u = bid*8 + k; warp half=w&1 covers
// j in [half*512, half*512+512), all 4 gates. Per-lane U = 4 gates x 16 j
// = 64 floats = 32 ull (fits 128-reg/thread budget at 512 thr).
// Per b: 4 LDS.128 + 32 fma2 + 6-shfl gate-fold + 1 STS of the half-partial.
// Pair combine via named barrier + zbuf; even warp does pointwise.
__global__ __launch_bounds__(NTHR9, 1) void lstm_rec9(const float* __restrict__ bias,
                                                      const float* __restrict__ xz,
                                                      float* __restrict__ out) {
    extern __shared__ float sh[];
    float* sh_h = sh;              // [32][1024] = 128 KB
    float* zbuf = sh + 32 * H;     // [16 warps][4 gates][33]
    const int tid  = threadIdx.x;
    const int lane = tid & 31;
    const int w    = tid >> 5;     // 0..15
    const int half = w & 1;
    const int u    = blockIdx.x * 8 + (w >> 1);

    // U slice -> registers (once): gate g, j = half*512 + m*128 + lane*4
    unsigned long long ur2[4][8];
#pragma unroll
    for (int g = 0; g < 4; g++)
#pragma unroll
        for (int m = 0; m < 4; m++) {
            ulonglong2 v = *(const ulonglong2*)(g_UT + ((size_t)(g * H + u)) * H
                                                + half * 512 + m * 128 + lane * 4);
            ur2[g][2 * m]     = v.x;
            ur2[g][2 * m + 1] = v.y;
        }
    const float b_i = bias[u], b_f = bias[H + u], b_g = bias[2 * H + u], b_o = bias[3 * H + u];
    float c = 0.f;

    const bool hi4 = (lane & 16) != 0;
    const bool hi3 = (lane & 8) != 0;

    unsigned sh_u32;
    {
        unsigned long long a = (unsigned long long)__cvta_generic_to_shared(sh_h);
        sh_u32 = (unsigned)a;
    }

    // prologue: stage h(0): 2 chunks x (8 x 16B per thread)
    {
        const float4* src = (const float4*)g_h[0];
#pragma unroll
        for (int chk = 0; chk < 2; chk++) {
#pragma unroll
            for (int k = 0; k < 8; k++) {
                int idx = chk * 4096 + k * 512 + tid;
                cp_async16(sh_u32 + idx * 16, src + idx);
            }
            cp_commit();
        }
    }

    for (int t = 0; t < TSTEPS; t++) {
        // input-projection prefetch (even warps only; lane plays batch role)
        float x0 = 0.f, x1 = 0.f, x2 = 0.f, x3 = 0.f;
        if (half == 0) {
            const size_t xbase = ((size_t)lane * TSTEPS + t) * (size_t)G4 + u;
            x0 = xz[xbase];
            x1 = xz[xbase + H];
            x2 = xz[xbase + 2 * H];
            x3 = xz[xbase + 3 * H];
        }

#pragma unroll
        for (int chk = 0; chk < 2; chk++) {
            if (chk == 0) cp_wait<1>();
            else cp_wait<0>();
            __syncthreads();

#pragma unroll 4
            for (int bb = 0; bb < 16; bb++) {
                const int b = chk * 16 + bb;
                unsigned long long a0 = 0ull, a1 = 0ull, a2 = 0ull, a3 = 0ull;
                const float* hb = sh_h + b * H + half * 512 + lane * 4;
#pragma unroll
                for (int m = 0; m < 4; m++) {
                    ulonglong2 hv = *(const ulonglong2*)(hb + m * 128);
                    fma2(a0, hv.x, ur2[0][2 * m]);
                    fma2(a1, hv.x, ur2[1][2 * m]);
                    fma2(a2, hv.x, ur2[2][2 * m]);
                    fma2(a3, hv.x, ur2[3][2 * m]);
                    fma2(a0, hv.y, ur2[0][2 * m + 1]);
                    fma2(a1, hv.y, ur2[1][2 * m + 1]);
                    fma2(a2, hv.y, ur2[2][2 * m + 1]);
                    fma2(a3, hv.y, ur2[3][2 * m + 1]);
                }
                float s0 = hsum2(a0), s1 = hsum2(a1), s2 = hsum2(a2), s3 = hsum2(a3);

                // gate-fold (gates -> lane bits 4,3) + butterfly: 6 shfl
                float t0 = hi4 ? s0 : s2;
                float t1 = hi4 ? s1 : s3;
                float r0 = __shfl_xor_sync(0xffffffffu, t0, 16);
                float r1 = __shfl_xor_sync(0xffffffffu, t1, 16);
                float u0 = (hi4 ? s2 : s0) + r0;
                float u1 = (hi4 ? s3 : s1) + r1;
                float t2 = hi3 ? u0 : u1;
                float r2 = __shfl_xor_sync(0xffffffffu, t2, 8);
                float v = (hi3 ? u1 : u0) + r2;   // gate = (lane>>3)&3
                v += __shfl_xor_sync(0xffffffffu, v, 4);
                v += __shfl_xor_sync(0xffffffffu, v, 2);
                v += __shfl_xor_sync(0xffffffffu, v, 1);
                // one writer per gate group: lane&7 == b&7
                if ((lane & 7) == (b & 7))
                    zbuf[w * 132 + (lane >> 3) * 33 + b] = v;
            }
        }

        // combine pair halves + pointwise (even warp; lane = batch)
        asm volatile("bar.sync %0, 64;" :: "r"((w >> 1) + 1) : "memory");
        float hval = 0.f;
        if (half == 0) {
            const int zw0 = w * 132, zw1 = (w + 1) * 132;
            float zi = zbuf[zw0 + lane]      + zbuf[zw1 + lane]      + x0 + b_i;
            float zf = zbuf[zw0 + 33 + lane] + zbuf[zw1 + 33 + lane] + x1 + b_f;
            float zg = zbuf[zw0 + 66 + lane] + zbuf[zw1 + 66 + lane] + x2 + b_g;
            float zo = zbuf[zw0 + 99 + lane] + zbuf[zw1 + 99 + lane] + x3 + b_o;

            const float ig = 1.f / (1.f + __expf(-zi));
            const float fg = 1.f / (1.f + __expf(-zf));
            const float gv = tanhf(zg);
            const float og = 1.f / (1.f + __expf(-zo));

            c = fg * c + ig * gv;
            hval = og * tanhf(c);

            out[((size_t)lane * TSTEPS + t) * H + u] = hval;
            g_h[(t + 1) & 1][(size_t)lane * H + u] = hval;
        }

        if (t == TSTEPS - 1) break;

        // ---- grid barrier: monotonic epoch counters, direct polling ----
        __threadfence();
        __syncthreads();
        const unsigned epoch = (unsigned)(t + 1);
        if (tid == 0) atomicAdd(&g_bar_cnt[(blockIdx.x & 7) * 32], 1u);
        if (tid < 32) {
            const unsigned need = epoch * (NCTA9 / 8);
            bool done;
            do {
                done = (lane >= 8) || (ld_cg_u32(&g_bar_cnt[lane * 32]) >= need);
            } while (!__all_sync(0xffffffffu, done));
            __threadfence();
        }
        __syncthreads();

        // ---- stage h(t+1): 2 chunks, consumed chunk-by-chunk next iteration ----
        {
            const float4* src = (const float4*)g_h[(t + 1) & 1];
#pragma unroll
            for (int chk = 0; chk < 2; chk++) {
#pragma unroll
                for (int k = 0; k < 8; k++) {
                    int idx = chk * 4096 + k * 512 + tid;
                    cp_async16(sh_u32 + idx * 16, src + idx);
                }
                cp_commit();
            }
        }
    }
}

// ---------------- launch ----------------
extern "C" void kernel_launch(void* const* d_in, const int* in_sizes, int n_in,
                              void* d_out, int out_size) {
    const float* x    = (const float*)d_in[0];  // [32,512,512]
    const float* W    = (const float*)d_in[1];  // [512,4096]
    const float* U    = (const float*)d_in[2];  // [1024,4096]
    const float* bias = (const float*)d_in[3];  // [4096]
    float* out = (float*)d_out;                 // [32,512,1024]

    static const int rec_smem = (32 * H + 16 * 132) * (int)sizeof(float);
    cudaFuncSetAttribute(lstm_rec9, cudaFuncAttributeMaxDynamicSharedMemorySize, rec_smem);

    float* xz_dev = nullptr;
    cudaGetSymbolAddress((void**)&xz_dev, g_xz);

    zero_h_kernel<<<(2 * BATCH * H + 255) / 256, 256>>>();
    transpose_u_kernel<<<dim3(G4 / 32, H / 32), dim3(32, 32)>>>(U);
    sgemm_xw_kernel<<<dim3(G4 / 128, (BATCH * TSTEPS) / 128), 256>>>(x, W);
    lstm_rec9<<<NCTA9, NTHR9, rec_smem>>>(bias, xz_dev, out);
}

// round 11
// speedup vs baseline: 1.1130x; 1.1130x over previous
#include <cuda_runtime.h>
#include <math.h>

#define H      1024
#define BATCH  32
#define TSTEPS 512
#define INDIM  512
#define G4     (4*H)
#define NCTA3  128
#define NTHR3  256   // 8 warps; warp = 1 unit

// ---------------- scratch ----------------
__device__ float g_xz[(size_t)BATCH * TSTEPS * G4];   // 268 MB: x@W, [B*T, 4H]
__device__ float g_UT[(size_t)G4 * H];                // 16 MB: U transposed [4H][H]
__device__ float g_h[2][BATCH * H];                   // ping-pong h, [b][j]
__device__ unsigned g_bar_cnt[8 * 32];                // 8 monotonic epoch counters, 128B stride

// ---------------- helpers ----------------
__device__ __forceinline__ void fma2(unsigned long long& d, unsigned long long a,
                                     unsigned long long b) {
    asm("fma.rn.f32x2 %0, %1, %2, %0;" : "+l"(d) : "l"(a), "l"(b));
}
__device__ __forceinline__ float hsum2(unsigned long long v) {
    float x, y;
    asm("mov.b64 {%0, %1}, %2;" : "=f"(x), "=f"(y) : "l"(v));
    return x + y;
}
__device__ __forceinline__ unsigned long long packdup(float a) {
    unsigned long long d;
    asm("mov.b64 %0, {%1, %1};" : "=l"(d) : "f"(a));
    return d;
}
__device__ __forceinline__ unsigned ld_cg_u32(const unsigned* p) {
    unsigned v;
    asm volatile("ld.global.cg.u32 %0, [%1];" : "=r"(v) : "l"(p) : "memory");
    return v;
}
__device__ __forceinline__ void cp_async16(unsigned smem_addr, const void* gptr) {
    asm volatile("cp.async.cg.shared.global [%0], [%1], 16;"
                 :: "r"(smem_addr), "l"(gptr) : "memory");
}
__device__ __forceinline__ void cp_commit() {
    asm volatile("cp.async.commit_group;" ::: "memory");
}
template <int N>
__device__ __forceinline__ void cp_wait() {
    asm volatile("cp.async.wait_group %0;" :: "n"(N) : "memory");
}

// ---------------- prep: zero h0 + barrier state (every replay) ----------------
__global__ void zero_h_kernel() {
    int i = blockIdx.x * blockDim.x + threadIdx.x;
    if (i < 2 * BATCH * H) ((float*)g_h)[i] = 0.f;
    if (i < 8 * 32) g_bar_cnt[i] = 0u;
}

// ---------------- transpose U [H][4H] -> UT [4H][H] ----------------
__global__ void transpose_u_kernel(const float* __restrict__ U) {
    __shared__ float tile[32][33];
    int x = blockIdx.x * 32 + threadIdx.x;
    int y = blockIdx.y * 32 + threadIdx.y;
    tile[threadIdx.y][threadIdx.x] = U[(size_t)y * G4 + x];
    __syncthreads();
    int ox = blockIdx.y * 32 + threadIdx.x;
    int oy = blockIdx.x * 32 + threadIdx.y;
    g_UT[(size_t)oy * H + ox] = tile[threadIdx.x][threadIdx.y];
}

// ---------------- input GEMM: g_xz = x @ W (f32x2 packed) ----------------
__global__ __launch_bounds__(256) void sgemm_xw_kernel(const float* __restrict__ A,
                                                       const float* __restrict__ Bm) {
    const int K = INDIM, N = G4;
    __shared__ float As[8][128];
    __shared__ float Bs[8][128];
    const int tid = threadIdx.x;
    const int bm = blockIdx.y, bn = blockIdx.x;
    const int arow = tid >> 1, acol = (tid & 1) << 2;
    const int brow = tid >> 5, bcol = (tid & 31) << 2;
    const int tx = tid & 15, ty = tid >> 4;

    unsigned long long acc2[4][8];
#pragma unroll
    for (int i = 0; i < 4; i++)
#pragma unroll
        for (int j = 0; j < 8; j++) acc2[i][j] = 0ull;

    const float* Ap = A + (size_t)(bm * 128 + arow) * K + acol;
    const float* Bp = Bm + (size_t)brow * N + bn * 128 + bcol;

    for (int k0 = 0; k0 < K; k0 += 8) {
        float4 av = *(const float4*)(Ap + k0);
        As[acol + 0][arow] = av.x;
        As[acol + 1][arow] = av.y;
        As[acol + 2][arow] = av.z;
        As[acol + 3][arow] = av.w;
        float4 bv = *(const float4*)(Bp + (size_t)k0 * N);
        *(float4*)&Bs[brow][bcol] = bv;
        __syncthreads();
#pragma unroll
        for (int kk = 0; kk < 8; kk++) {
            ulonglong2 a01 = *(const ulonglong2*)&As[kk][ty * 8];
            ulonglong2 a23 = *(const ulonglong2*)&As[kk][ty * 8 + 4];
            unsigned long long a2[4] = {a01.x, a01.y, a23.x, a23.y};
            float4 b0 = *(const float4*)&Bs[kk][tx * 8];
            float4 b1 = *(const float4*)&Bs[kk][tx * 8 + 4];
            unsigned long long b2[8];
            b2[0] = packdup(b0.x); b2[1] = packdup(b0.y);
            b2[2] = packdup(b0.z); b2[3] = packdup(b0.w);
            b2[4] = packdup(b1.x); b2[5] = packdup(b1.y);
            b2[6] = packdup(b1.z); b2[7] = packdup(b1.w);
#pragma unroll
            for (int i = 0; i < 4; i++)
#pragma unroll
                for (int j = 0; j < 8; j++) fma2(acc2[i][j], a2[i], b2[j]);
        }
        __syncthreads();
    }
    float* Cp = g_xz + (size_t)(bm * 128 + ty * 8) * N + bn * 128 + tx * 8;
#pragma unroll
    for (int i = 0; i < 4; i++) {
        float r0[8], r1[8];
#pragma unroll
        for (int j = 0; j < 8; j++) {
            float x, y;
            asm("mov.b64 {%0, %1}, %2;" : "=f"(x), "=f"(y) : "l"(acc2[i][j]));
            r0[j] = x; r1[j] = y;
        }
        *(float4*)(Cp + (size_t)(2 * i) * N)     = make_float4(r0[0], r0[1], r0[2], r0[3]);
        *(float4*)(Cp + (size_t)(2 * i) * N + 4) = make_float4(r0[4], r0[5], r0[6], r0[7]);
        *(float4*)(Cp + (size_t)(2 * i + 1) * N)     = make_float4(r1[0], r1[1], r1[2], r1[3]);
        *(float4*)(Cp + (size_t)(2 * i + 1) * N + 4) = make_float4(r1[4], r1[5], r1[6], r1[7]);
    }
}

// ---------------- persistent recurrent kernel v10 ----------------
// R7 skeleton. New: chunk-level register fold — accumulate all 32 (gate,b)
// values of an 8-b chunk, then ONE 5-round exchange-fold (31 shfl) producing
// all 32 sums distributed one per lane (lane = g*8 + bb). 1 STS/lane/chunk
// into padded zbuf; pointwise (lane = batch) reads 4 gates from zbuf.
__global__ __launch_bounds__(NTHR3, 1) void lstm_rec10(const float* __restrict__ bias,
                                                       const float* __restrict__ xz,
                                                       float* __restrict__ out) {
    extern __shared__ float sh[];
    float* sh_h = sh;              // [32][1024] = 128 KB
    float* zbuf = sh + 32 * H;     // [8 warps][4 gates][33]
    const int tid  = threadIdx.x;
    const int lane = tid & 31;
    const int w    = tid >> 5;
    const int u    = blockIdx.x * 8 + w;

    // U slice -> registers (once)
    unsigned long long ur2[4][16];
#pragma unroll
    for (int g = 0; g < 4; g++)
#pragma unroll
        for (int m = 0; m < 8; m++) {
            ulonglong2 v = *(const ulonglong2*)(g_UT + ((size_t)(g * H + u)) * H
                                                + m * 128 + lane * 4);
            ur2[g][2 * m]     = v.x;
            ur2[g][2 * m + 1] = v.y;
        }
    const float b_i = bias[u], b_f = bias[H + u], b_g = bias[2 * H + u], b_o = bias[3 * H + u];
    float c = 0.f;

    const bool hi4 = (lane & 16) != 0;
    const bool hi3 = (lane & 8) != 0;
    const bool hi2 = (lane & 4) != 0;
    const bool hi1 = (lane & 2) != 0;
    const bool hi0 = (lane & 1) != 0;

    unsigned sh_u32;
    {
        unsigned long long a = (unsigned long long)__cvta_generic_to_shared(sh_h);
        sh_u32 = (unsigned)a;
    }

    // prologue: stage h(0): 4 chunks x (8 x 16B per thread)
    {
        const float4* src = (const float4*)g_h[0];
#pragma unroll
        for (int chk = 0; chk < 4; chk++) {
#pragma unroll
            for (int k = 0; k < 8; k++) {
                int idx = chk * 2048 + k * 256 + tid;
                cp_async16(sh_u32 + idx * 16, src + idx);
            }
            cp_commit();
        }
    }

    for (int t = 0; t < TSTEPS; t++) {
        // input-projection prefetch (lane plays batch role)
        const size_t xbase = ((size_t)lane * TSTEPS + t) * (size_t)G4 + u;
        const float x0 = xz[xbase];
        const float x1 = xz[xbase + H];
        const float x2 = xz[xbase + 2 * H];
        const float x3 = xz[xbase + 3 * H];

#pragma unroll
        for (int chk = 0; chk < 4; chk++) {
            if (chk == 0) cp_wait<3>();
            else if (chk == 1) cp_wait<2>();
            else if (chk == 2) cp_wait<1>();
            else cp_wait<0>();
            __syncthreads();

            // accumulate whole chunk: acc[g][bb], 32 packed accumulators
            unsigned long long acc[4][8];
#pragma unroll
            for (int g = 0; g < 4; g++)
#pragma unroll
                for (int bb = 0; bb < 8; bb++) acc[g][bb] = 0ull;

#pragma unroll
            for (int bb = 0; bb < 8; bb++) {
                const float* hb = sh_h + (chk * 8 + bb) * H + lane * 4;
#pragma unroll
                for (int m = 0; m < 8; m++) {
                    ulonglong2 hv = *(const ulonglong2*)(hb + m * 128);
                    fma2(acc[0][bb], hv.x, ur2[0][2 * m]);
                    fma2(acc[1][bb], hv.x, ur2[1][2 * m]);
                    fma2(acc[2][bb], hv.x, ur2[2][2 * m]);
                    fma2(acc[3][bb], hv.x, ur2[3][2 * m]);
                    fma2(acc[0][bb], hv.y, ur2[0][2 * m + 1]);
                    fma2(acc[1][bb], hv.y, ur2[1][2 * m + 1]);
                    fma2(acc[2][bb], hv.y, ur2[2][2 * m + 1]);
                    fma2(acc[3][bb], hv.y, ur2[3][2 * m + 1]);
                }
            }

            // horizontal sums: x[index], index = g*8 + bb
            float xr[32];
#pragma unroll
            for (int g = 0; g < 4; g++)
#pragma unroll
                for (int bb = 0; bb < 8; bb++) xr[g * 8 + bb] = hsum2(acc[g][bb]);

            // 5-round exchange-fold (31 shfl): lane keeps high half iff its bit=1
#pragma unroll
            for (int i = 0; i < 16; i++) {
                float s = hi4 ? xr[i] : xr[i + 16];
                float r = __shfl_xor_sync(0xffffffffu, s, 16);
                xr[i] = (hi4 ? xr[i + 16] : xr[i]) + r;
            }
#pragma unroll
            for (int i = 0; i < 8; i++) {
                float s = hi3 ? xr[i] : xr[i + 8];
                float r = __shfl_xor_sync(0xffffffffu, s, 8);
                xr[i] = (hi3 ? xr[i + 8] : xr[i]) + r;
            }
#pragma unroll
            for (int i = 0; i < 4; i++) {
                float s = hi2 ? xr[i] : xr[i + 4];
                float r = __shfl_xor_sync(0xffffffffu, s, 4);
                xr[i] = (hi2 ? xr[i + 4] : xr[i]) + r;
            }
#pragma unroll
            for (int i = 0; i < 2; i++) {
                float s = hi1 ? xr[i] : xr[i + 2];
                float r = __shfl_xor_sync(0xffffffffu, s, 2);
                xr[i] = (hi1 ? xr[i + 2] : xr[i]) + r;
            }
            float v;
            {
                float s = hi0 ? xr[0] : xr[1];
                float r = __shfl_xor_sync(0xffffffffu, s, 1);
                v = (hi0 ? xr[1] : xr[0]) + r;
            }
            // lane holds z for gate = lane>>3, b = chk*8 + (lane&7)
            zbuf[w * 132 + (lane >> 3) * 33 + chk * 8 + (lane & 7)] = v;
        }
        __syncwarp();

        // pointwise (lane = batch)
        const int zw = w * 132;
        float zi = zbuf[zw + lane]      + x0 + b_i;
        float zf = zbuf[zw + 33 + lane] + x1 + b_f;
        float zg = zbuf[zw + 66 + lane] + x2 + b_g;
        float zo = zbuf[zw + 99 + lane] + x3 + b_o;

        const float ig = 1.f / (1.f + __expf(-zi));
        const float fg = 1.f / (1.f + __expf(-zf));
        const float gv = tanhf(zg);
        const float og = 1.f / (1.f + __expf(-zo));

        c = fg * c + ig * gv;
        const float hval = og * tanhf(c);

        out[((size_t)lane * TSTEPS + t) * H + u] = hval;
        g_h[(t + 1) & 1][(size_t)lane * H + u] = hval;

        if (t == TSTEPS - 1) break;

        // ---- grid barrier: monotonic epoch counters, direct polling ----
        __threadfence();
        __syncthreads();
        const unsigned epoch = (unsigned)(t + 1);
        if (tid == 0) atomicAdd(&g_bar_cnt[(blockIdx.x & 7) * 32], 1u);
        if (tid < 32) {
            const unsigned need = epoch * (NCTA3 / 8);
            bool done;
            do {
                done = (lane >= 8) || (ld_cg_u32(&g_bar_cnt[lane * 32]) >= need);
            } while (!__all_sync(0xffffffffu, done));
            __threadfence();
        }
        __syncthreads();

        // ---- stage h(t+1): 4 chunks, consumed chunk-by-chunk next iteration ----
        {
            const float4* src = (const float4*)g_h[(t + 1) & 1];
#pragma unroll
            for (int chk = 0; chk < 4; chk++) {
#pragma unroll
                for (int k = 0; k < 8; k++) {
                    int idx = chk * 2048 + k * 256 + tid;
                    cp_async16(sh_u32 + idx * 16, src + idx);
                }
                cp_commit();
            }
        }
    }
}

// ---------------- launch ----------------
extern "C" void kernel_launch(void* const* d_in, const int* in_sizes, int n_in,
                              void* d_out, int out_size) {
    const float* x    = (const float*)d_in[0];  // [32,512,512]
    const float* W    = (const float*)d_in[1];  // [512,4096]
    const float* U    = (const float*)d_in[2];  // [1024,4096]
    const float* bias = (const float*)d_in[3];  // [4096]
    float* out = (float*)d_out;                 // [32,512,1024]

    static const int rec_smem = (32 * H + 8 * 132) * (int)sizeof(float);
    cudaFuncSetAttribute(lstm_rec10, cudaFuncAttributeMaxDynamicSharedMemorySize, rec_smem);

    float* xz_dev = nullptr;
    cudaGetSymbolAddress((void**)&xz_dev, g_xz);

    zero_h_kernel<<<(2 * BATCH * H + 255) / 256, 256>>>();
    transpose_u_kernel<<<dim3(G4 / 32, H / 32), dim3(32, 32)>>>(U);
    sgemm_xw_kernel<<<dim3(G4 / 128, (BATCH * TSTEPS) / 128), 256>>>(x, W);
    lstm_rec10<<<NCTA3, NTHR3, rec_smem>>>(bias, xz_dev, out);
}